// round 11
// baseline (speedup 1.0000x reference)
#include <cuda_runtime.h>
#include <cuda_fp16.h>
#include <cstdint>

using f16 = __half;

// ---------------------------------------------------------------------------
// Scratch layout (fp16 hi/lo pairs: components at +0 and +cs)
// ---------------------------------------------------------------------------
constexpr long SZ    = 262144;                 // 512*512
constexpr long O_P   = 0;          constexpr long CS_P  = 11 * SZ;  // A^(2^j) j=0..10
constexpr long O_PT  = 22 * SZ;                                     // transposes
constexpr long O_W   = 44 * SZ;    constexpr long CS_W  = 4 * SZ;   // W 512x2048
constexpr long O_WT  = 52 * SZ;                                     // Wt 2048x512
constexpr long O_U   = 60 * SZ;    constexpr long CS_U  = 2 * SZ;   // U 256x2048
constexpr long O_PC  = 64 * SZ;    constexpr long CS_PC = SZ / 2;   // Pc 256x512
constexpr long O_F   = 65 * SZ;    constexpr long CS_F  = 2 * SZ;   // folds 8x128x512
constexpr long FLVL  = 65536;                  // 128 rows x 512 per fold level
constexpr long HTOT  = 69 * SZ;

constexpr int OF_PC  = 0;                      // chunk fp32 split-K accumulator
constexpr int OF_V   = 131072;                 // 306 x 256 weighted vectors
constexpr int OF_UAC = OF_V + 306 * 256;
constexpr int FTOT   = OF_UAC + 256;

__device__ __align__(16) f16   g_h[HTOT];
__device__ __align__(16) float g_f[FTOT];
__device__ unsigned g_bar2;

// ---------------------------------------------------------------------------
__device__ __forceinline__ void split2(float v, f16& h, f16& l) {
  h = __float2half_rn(v);
  l = __float2half_rn(v - __half2float(h));
}

// Merged head: cvtA | cvtB | cvtU | zero, branched on blockIdx.x
__global__ void k_init(const float* __restrict__ A, const float* __restrict__ B,
                       const float* __restrict__ uh)
{
  const int b = blockIdx.x, t = threadIdx.x;
  if (b < 1024) {                       // A -> P0 + PT0
    int i = b * 256 + t;
    f16 h, l; split2(A[i], h, l);
    int r = i >> 9, k = i & 511;
    g_h[O_P + i] = h; g_h[O_P + CS_P + i] = l;
    long tr = O_PT + (long)k * 512 + r;
    g_h[tr] = h; g_h[tr + CS_P] = l;
  } else if (b < 1536) {                // B -> W block7 + WT block7
    int i = (b - 1024) * 256 + t;
    f16 h, l; split2(B[i], h, l);
    int d = i >> 8, n = i & 255;
    long w = O_W + (long)d * 2048 + 1792 + n;
    g_h[w] = h; g_h[w + CS_W] = l;
    long tr = O_WT + (long)(1792 + n) * 512 + d;
    g_h[tr] = h; g_h[tr + CS_W] = l;
  } else if (b < 3584) {                // u_history -> U pair
    int i = (b - 1536) * 256 + t;
    f16 h, l; split2(uh[i], h, l);
    g_h[O_U + i] = h; g_h[O_U + CS_U + i] = l;
  } else {                              // zero fp32 scratch + fold region
    if (b == 3584 && t == 0) g_bar2 = 0;
    long i = (long)(b - 3584) * 256 + t;
    if (i < FTOT / 4) ((float4*)g_f)[i] = make_float4(0.f, 0.f, 0.f, 0.f);
    long j = i - FTOT / 4;
    if (j >= 0 && j < SZ / 2)
      ((uint4*)(g_h + O_F))[j] = make_uint4(0u, 0u, 0u, 0u);
  }
}

__global__ void k_cvtP() {
  int i = blockIdx.x * 256 + threadIdx.x;              // 131072
  f16 h, l; split2(g_f[OF_PC + i], h, l);
  g_h[O_PC + i] = h; g_h[O_PC + CS_PC + i] = l;
}

// ---------------------------------------------------------------------------
// Tensor-core GEMM (NT): C[m][n] = sum_k A[m][k]*Bt[n][k]  (+addsrc pair)
// fp16 2-way split, 3 products (hh, hl, lh), fp32 accumulate.
// CTA tile 64x32, full K=512 smem-resident, 256 threads = 8 warps:
// kg2 x wm2 x wn2, warp tile m32 x n16 (4 independent acc atoms).
// ---------------------------------------------------------------------------
__device__ __forceinline__ void mma16816(float* c, const uint32_t* a, const uint32_t* b) {
  asm volatile(
    "mma.sync.aligned.m16n8k16.row.col.f32.f16.f16.f32 "
    "{%0,%1,%2,%3},{%4,%5,%6,%7},{%8,%9},{%0,%1,%2,%3};\n"
    : "+f"(c[0]), "+f"(c[1]), "+f"(c[2]), "+f"(c[3])
    : "r"(a[0]), "r"(a[1]), "r"(a[2]), "r"(a[3]), "r"(b[0]), "r"(b[1]));
}

__device__ __forceinline__ void ldsm4(uint32_t& r0, uint32_t& r1, uint32_t& r2,
                                      uint32_t& r3, uint32_t addr) {
  asm volatile("ldmatrix.sync.aligned.m8n8.x4.shared.b16 {%0,%1,%2,%3}, [%4];"
               : "=r"(r0), "=r"(r1), "=r"(r2), "=r"(r3) : "r"(addr));
}

__device__ __forceinline__ uint32_t s2u(const void* p) {
  uint32_t a;
  asm("{ .reg .u64 t; cvta.to.shared.u64 t, %1; cvt.u32.u64 %0, t; }"
      : "=r"(a) : "l"(p));
  return a;
}

__device__ __forceinline__ void cpa16(uint32_t d, const void* s) {
  asm volatile("cp.async.cg.shared.global [%0], [%1], 16;" :: "r"(d), "l"(s));
}

constexpr int LSK    = 520;            // full-K padded stride (halves)
constexpr int A_HLV  = 64 * LSK;       // per-component A region (halves)
constexpr int B_HLV  = 32 * LSK;
constexpr int B_OFF  = 2 * A_HLV;      // halves offset of B region
constexpr int DSM    = (2 * A_HLV + 2 * B_HLV) * 2;   // 199680 bytes

__global__ void __launch_bounds__(256) k_mma(
    const f16* __restrict__ A, long csA, int lda,
    const f16* __restrict__ B, long csB, int ldb,
    f16* C, long csC, int ldc, f16* Ct, int ldct, int ksl,
    const f16* __restrict__ ad, long csAd, int ldad, float* Cf)
{
  extern __shared__ __align__(16) char smem[];
  const int tid = threadIdx.x, lane = tid & 31, warp = tid >> 5;
  const int kg = warp >> 2, w4 = warp & 3;
  const int wm = w4 & 1, wn = w4 >> 1;       // warp tile m32 x n16
  const int bm = blockIdx.y * 64, bn = blockIdx.x * 32;
  const long k0 = (long)blockIdx.z * ksl;    // ksl == 512 always
  const int G = lane >> 2, T = lane & 3;
  const uint32_t sb = s2u(smem);
  float acc[2][2][4] = {};                   // [mt][nt][4]

  // ldmatrix per-thread byte offsets (within a component plane)
  const int aRowL = ((lane >> 3) & 1) * 8 + (lane & 7);
  const int aColL = ((lane >> 4) & 1) * 8;
  uint32_t aOff[2];
  aOff[0] = (uint32_t)((wm * 32 + aRowL) * LSK + aColL) * 2;
  aOff[1] = (uint32_t)((wm * 32 + 16 + aRowL) * LSK + aColL) * 2;
  const int bRowL = ((lane >> 4) & 1) * 8 + (lane & 7);
  const int bColL = ((lane >> 3) & 1) * 8;
  const uint32_t bOff = (uint32_t)((wn * 16 + bRowL) * LSK + bColL) * 2;

  // ---- issue ALL loads up front ----
  {
    const int row0 = tid >> 3, colb = (tid & 7) * 8;
#pragma unroll
    for (int c = 0; c < 2; c++) {
#pragma unroll
      for (int rg = 0; rg < 2; rg++) {
        const int row = row0 + rg * 32;
        const f16* Ag = A + c * csA + (long)(bm + row) * lda + k0 + colb;
        const uint32_t da = sb + (uint32_t)(c * A_HLV + row * LSK + colb) * 2;
#pragma unroll
        for (int kq = 0; kq < 8; kq++)
          cpa16(da + kq * 128, Ag + kq * 64);
      }
      const f16* Bg = B + c * csB + (long)(bn + row0) * ldb + k0 + colb;
      const uint32_t db = sb + (uint32_t)(B_OFF + c * B_HLV + row0 * LSK + colb) * 2;
#pragma unroll
      for (int kq = 0; kq < 8; kq++)
        cpa16(db + kq * 128, Bg + kq * 64);
    }
    asm volatile("cp.async.commit_group;");
    asm volatile("cp.async.wait_group 0;" ::: "memory");
    __syncthreads();
  }

  // ---- straight-line compute: 16 k-chunks of 16 per warp ----
#pragma unroll 4
  for (int it = 0; it < 16; it++) {
    const int kk = it * 32 + kg * 16;
    uint32_t aF[2][2][4], bF[2][2][2];
#pragma unroll
    for (int c = 0; c < 2; c++) {
#pragma unroll
      for (int mt = 0; mt < 2; mt++)
        ldsm4(aF[c][mt][0], aF[c][mt][1], aF[c][mt][2], aF[c][mt][3],
              sb + (uint32_t)(c * A_HLV + kk) * 2 + aOff[mt]);
      ldsm4(bF[c][0][0], bF[c][0][1], bF[c][1][0], bF[c][1][1],
            sb + (uint32_t)(B_OFF + c * B_HLV + kk) * 2 + bOff);
    }
#pragma unroll
    for (int mt = 0; mt < 2; mt++)
#pragma unroll
      for (int nt = 0; nt < 2; nt++) {
        mma16816(acc[mt][nt], aF[0][mt], bF[0][nt]);   // hh
        mma16816(acc[mt][nt], aF[0][mt], bF[1][nt]);   // hl
        mma16816(acc[mt][nt], aF[1][mt], bF[0][nt]);   // lh
      }
  }
  __syncthreads();                      // before smem reuse for reduction

  // ---- kg split-K reduction through smem (64x33 fp32) ----
  float* red = (float*)smem;
  if (kg) {
#pragma unroll
    for (int mt = 0; mt < 2; mt++)
#pragma unroll
      for (int nt = 0; nt < 2; nt++)
#pragma unroll
        for (int h2 = 0; h2 < 2; h2++) {
          const int rl = wm * 32 + mt * 16 + G + h2 * 8;
          const int cl = wn * 16 + nt * 8 + T * 2;
          red[rl * 33 + cl]     = acc[mt][nt][h2 * 2];
          red[rl * 33 + cl + 1] = acc[mt][nt][h2 * 2 + 1];
        }
  }
  __syncthreads();
  if (!kg) {
#pragma unroll
    for (int mt = 0; mt < 2; mt++)
#pragma unroll
      for (int nt = 0; nt < 2; nt++)
#pragma unroll
        for (int h2 = 0; h2 < 2; h2++) {
          const int rl = wm * 32 + mt * 16 + G + h2 * 8;
          const int cl = wn * 16 + nt * 8 + T * 2;
          acc[mt][nt][h2 * 2]     += red[rl * 33 + cl];
          acc[mt][nt][h2 * 2 + 1] += red[rl * 33 + cl + 1];
        }
  }

  if (Cf) {
    if (!kg) {
#pragma unroll
      for (int mt = 0; mt < 2; mt++)
#pragma unroll
        for (int nt = 0; nt < 2; nt++)
#pragma unroll
          for (int h2 = 0; h2 < 2; h2++) {
            const int r = bm + wm * 32 + mt * 16 + G + h2 * 8;
            const int c0 = bn + wn * 16 + nt * 8 + T * 2;
            atomicAdd(&Cf[(long)r * ldc + c0],     acc[mt][nt][h2 * 2]);
            atomicAdd(&Cf[(long)r * ldc + c0 + 1], acc[mt][nt][h2 * 2 + 1]);
          }
    }
    return;
  }

  if (!kg) {
#pragma unroll
    for (int mt = 0; mt < 2; mt++)
#pragma unroll
      for (int nt = 0; nt < 2; nt++)
#pragma unroll
        for (int h2 = 0; h2 < 2; h2++) {
          const int rl = wm * 32 + mt * 16 + G + h2 * 8;
          const int cl = wn * 16 + nt * 8 + T * 2;
          const int r = bm + rl, c0 = bn + cl;
          float v0 = acc[mt][nt][h2 * 2], v1 = acc[mt][nt][h2 * 2 + 1];
          if (ad) {
            const long o0 = (long)r * ldad + c0;
            v0 += __half2float(ad[o0])     + __half2float(ad[csAd + o0]);
            v1 += __half2float(ad[o0 + 1]) + __half2float(ad[csAd + o0 + 1]);
          }
          f16 h0, l0, h1, l1;
          split2(v0, h0, l0); split2(v1, h1, l1);
          __half2 t;
          t.x = h0; t.y = h1; *(__half2*)&C[(long)r * ldc + c0] = t;
          t.x = l0; t.y = l1; *(__half2*)&C[csC + (long)r * ldc + c0] = t;
          if (Ct) { red[rl * 33 + cl] = v0; red[rl * 33 + cl + 1] = v1; }
        }
  }

  if (Ct) {
    __syncthreads();
    const int cl = tid >> 3, rb = (tid & 7) * 8;   // col 0..31, row block
    const long cb = (long)(bn + cl) * ldct + bm + rb;
#pragma unroll
    for (int j = 0; j < 8; j += 2) {
      float a0 = red[(rb + j) * 33 + cl];
      float a1 = red[(rb + j + 1) * 33 + cl];
      f16 h0, l0, h1, l1;
      split2(a0, h0, l0); split2(a1, h1, l1);
      __half2 t;
      t.x = h0; t.y = h1; *(__half2*)&Ct[cb + j] = t;
      t.x = l0; t.y = l1; *(__half2*)&Ct[csC + cb + j] = t;
    }
  }
}

// ---------------------------------------------------------------------------
// Fused tail: folds 5..7 (fp32 SIMT matvecs, grid-synced) + finish.
// All CTAs resident (no smem, grid 128 <= SM count).
// ---------------------------------------------------------------------------
__global__ void __launch_bounds__(256) k_tail(
    const float* __restrict__ Cm, const float* __restrict__ yh, float* __restrict__ out)
{
  const int lane = threadIdx.x & 31;
  const int w = blockIdx.x * 8 + (threadIdx.x >> 5);
  const int NW = gridDim.x * 8;

  for (int l = 5; l <= 7; l++) {
    const int nv = 256 >> (l + 1);             // 4, 2, 1 output vectors
    const long pb = O_P + (long)(3 + l) * SZ;  // A^(8*2^l)
    const long inb = O_F + (long)(l - 1) * FLVL;
    for (int d = w; d < nv * 512; d += NW) {
      const int o = d >> 9, m = d & 511;
      float acc = 0.f;
#pragma unroll
      for (int j = 0; j < 16; j++) {
        const int k = lane + 32 * j;
        float pv = __half2float(g_h[pb + (long)m * 512 + k]) +
                   __half2float(g_h[pb + CS_P + (long)m * 512 + k]);
        float iv = __half2float(g_h[inb + (long)(2 * o) * 512 + k]) +
                   __half2float(g_h[inb + CS_F + (long)(2 * o) * 512 + k]);
        acc += pv * iv;
      }
#pragma unroll
      for (int off = 16; off; off >>= 1) acc += __shfl_xor_sync(~0u, acc, off);
      if (lane == 0) {
        float i1 = __half2float(g_h[inb + (long)(2 * o + 1) * 512 + m]) +
                   __half2float(g_h[inb + CS_F + (long)(2 * o + 1) * 512 + m]);
        float v = acc + i1;
        f16 h, lo; split2(v, h, lo);
        g_h[O_F + (long)l * FLVL + (long)o * 512 + m] = h;
        g_h[O_F + CS_F + (long)l * FLVL + (long)o * 512 + m] = lo;
      }
    }
    // software grid barrier
    __syncthreads();
    if (threadIdx.x == 0) {
      __threadfence();
      atomicAdd(&g_bar2, 1u);
      const unsigned tgt = gridDim.x * (unsigned)(l - 4);
      while (*((volatile unsigned*)&g_bar2) < tgt) {}
    }
    __syncthreads();
  }

  // finish: y_nat = yh[2047] - C s ; pred = y_nat + C v ; u_t copy
  if (w < 256) {
    const int r = w;
    const float* crow = Cm + r * 512;
    const long so = O_F + 7L * FLVL;
    const long vo = O_F + 127L * 512;
    float ds = 0.f, dv = 0.f;
#pragma unroll
    for (int j = 0; j < 16; j++) {
      const int k = lane + 32 * j; const float c = crow[k];
      ds += c * (__half2float(g_h[so + k]) + __half2float(g_h[so + CS_F + k]));
      dv += c * (__half2float(g_h[vo + k]) + __half2float(g_h[vo + CS_F + k]));
    }
#pragma unroll
    for (int off = 16; off; off >>= 1) {
      ds += __shfl_xor_sync(~0u, ds, off);
      dv += __shfl_xor_sync(~0u, dv, off);
    }
    if (lane == 0) {
      float yn = yh[2047 * 256 + r] - ds;
      out[r] = yn; out[256 + r] = yn + dv; out[512 + r] = g_f[OF_UAC + r];
    }
  }
}

// ---------------------------------------------------------------------------
// u_t phase (fp32, unchanged)
// ---------------------------------------------------------------------------
__global__ void k_prep(const float* __restrict__ ynh, const float* __restrict__ phi,
                       const float* __restrict__ pht, const float* __restrict__ sigma,
                       const float* __restrict__ lam)
{
  const int x = blockIdx.x, p = threadIdx.x;
  float* V = g_f + OF_V;
#define YREV(j) ynh[(2047 - (j)) * 256 + p]
  if (x == 0) {
    V[p] = YREV(0);
  } else if (x < 17) {
    int i = x - 1; float acc = 0.f;
    for (int j = 0; j < 24; j++) acc += pht[j * 16 + i] * YREV(1 + j);
    V[x * 256 + p] = sqrtf(sqrtf(lam[i])) * acc;
  } else if (x < 34) {
    int l = x - 17; float acc = 0.f;
    for (int k = 0; k < 25; k++) acc += phi[k * 17 + l] * YREV(k);
    V[x * 256 + p] = sqrtf(sqrtf(sigma[l])) * acc;
  } else {
    int idx = x - 34, i = idx / 17, l = idx % 17;
    __shared__ float cm[48];
    if (p < 48) {
      int jlo = p > 24 ? p - 24 : 0, jhi = p < 23 ? p : 23;
      float s = 0.f;
      for (int j = jlo; j <= jhi; j++) s += pht[j * 16 + i] * phi[(p - j) * 17 + l];
      cm[p] = s;
    }
    __syncthreads();
    float acc = 0.f;
    for (int m = 0; m < 48; m++) acc += cm[m] * YREV(2 + m);
    V[x * 256 + p] = sqrtf(sqrtf(lam[i])) * sqrtf(sqrtf(sigma[l])) * acc;
  }
#undef YREV
}

__global__ void __launch_bounds__(256) k_matvec(
    const float* __restrict__ M, const float* __restrict__ Mbar)
{
  const int task = (blockIdx.x * 256 + threadIdx.x) >> 5;
  const int lane = threadIdx.x & 31;
  const int x = task >> 8, n = task & 255;
  const float* row = (x < 17 ? Mbar + x * 65536 : M + (x - 17) * 65536) + n * 256;
  const float* v = g_f + OF_V + x * 256;
  float acc = 0.f;
#pragma unroll
  for (int j = 0; j < 2; j++) {
    float4 a = ((const float4*)row)[lane + 32 * j];
    float4 b = ((const float4*)v)[lane + 32 * j];
    acc += a.x * b.x + a.y * b.y + a.z * b.z + a.w * b.w;
  }
#pragma unroll
  for (int off = 16; off; off >>= 1) acc += __shfl_xor_sync(~0u, acc, off);
  if (lane == 0) atomicAdd(&g_f[OF_UAC + n], acc);
}

// ---------------------------------------------------------------------------
static inline void mm(cudaStream_t st, dim3 g, const f16* A, long csA, int lda,
                      const f16* B, long csB, int ldb,
                      f16* C, long csC, int ldc, f16* Ct, int ldct, int ksl,
                      const f16* ad = nullptr, long csAd = 0, int ldad = 0,
                      float* Cf = nullptr)
{
  k_mma<<<g, 256, DSM, st>>>(A, csA, lda, B, csB, ldb, C, csC, ldc, Ct, ldct, ksl,
                             ad, csAd, ldad, Cf);
}

extern "C" void kernel_launch(void* const* d_in, const int* in_sizes, int n_in,
                              void* d_out, int out_size)
{
  const float* A   = (const float*)d_in[0];
  const float* Bm  = (const float*)d_in[1];
  const float* Cm  = (const float*)d_in[2];
  const float* Mi  = (const float*)d_in[3];
  const float* Mb  = (const float*)d_in[4];
  const float* sig = (const float*)d_in[5];
  const float* phi = (const float*)d_in[6];
  const float* lam = (const float*)d_in[7];
  const float* pht = (const float*)d_in[8];
  const float* yh  = (const float*)d_in[9];
  const float* uh  = (const float*)d_in[10];
  const float* ynh = (const float*)d_in[11];
  float* out = (float*)d_out;

  // One-time infra (created on the uncaptured correctness call; no device mem)
  static bool inited = false;
  static cudaStream_t s1, s2;
  static cudaEvent_t ev[16];
  if (!inited) {
    cudaStreamCreateWithFlags(&s1, cudaStreamNonBlocking);
    cudaStreamCreateWithFlags(&s2, cudaStreamNonBlocking);
    for (int i = 0; i < 16; i++)
      cudaEventCreateWithFlags(&ev[i], cudaEventDisableTiming);
    cudaFuncSetAttribute(k_mma, cudaFuncAttributeMaxDynamicSharedMemorySize, DSM);
    inited = true;
  }
  cudaStream_t s0 = 0;

  void* p;
  cudaGetSymbolAddress(&p, g_h); f16* H = (f16*)p;
  cudaGetSymbolAddress(&p, g_f); float* F = (float*)p;

  // ---- head (s0) ----
  k_init<<<4304, 256, 0, s0>>>(A, Bm, uh);
  cudaEventRecord(ev[0], s0);

  // ---- s0: squaring chain A^2 .. A^1024, event after each ----
  for (int j = 1; j <= 10; j++) {
    mm(s0, dim3(16, 8, 1), H + O_P + (j - 1) * SZ, CS_P, 512,
       H + O_PT + (j - 1) * SZ, CS_P, 512,
       H + O_P + j * SZ, CS_P, 512, H + O_PT + j * SZ, 512, 512);
    cudaEventRecord(ev[j], s0);
  }

  // ---- s2: u_t phase, fully parallel ----
  cudaStreamWaitEvent(s2, ev[0], 0);
  k_prep<<<306, 256, 0, s2>>>(ynh, phi, pht, sig, lam);
  k_matvec<<<306 * 32, 256, 0, s2>>>(Mi, Mb);
  cudaEventRecord(ev[14], s2);

  // ---- s1: W build -> chunk -> folds 0..4 ----
  cudaStreamWaitEvent(s1, ev[0], 0);
  // W block6 = A @ B (B operand = WT block7), dual-write WT block6
  mm(s1, dim3(8, 8, 1), H + O_P, CS_P, 512, H + O_WT + 1792L * 512, CS_W, 512,
     H + O_W + 1536, CS_W, 2048, H + O_WT + 1536L * 512, 512, 512);
  // W blocks 4,5 = A^2 @ blocks 6,7
  cudaStreamWaitEvent(s1, ev[1], 0);
  mm(s1, dim3(16, 8, 1), H + O_P + SZ, CS_P, 512, H + O_WT + 1536L * 512, CS_W, 512,
     H + O_W + 1024, CS_W, 2048, H + O_WT + 1024L * 512, 512, 512);
  // W blocks 0..3 = A^4 @ blocks 4..7
  cudaStreamWaitEvent(s1, ev[2], 0);
  mm(s1, dim3(32, 8, 1), H + O_P + 2 * SZ, CS_P, 512, H + O_WT + 1024L * 512, CS_W, 512,
     H + O_W, CS_W, 2048, H + O_WT, 512, 512);
  // chunk partials: Pc = U @ W^T, split-K=4, fp32 atomics
  mm(s1, dim3(16, 4, 4), H + O_U, CS_U, 2048, H + O_W, CS_W, 2048,
     nullptr, 0, 512, nullptr, 0, 512, nullptr, 0, 0, F + OF_PC);
  k_cvtP<<<512, 256, 0, s1>>>();
  // fold levels 0..4: out[m] = A^(8*2^l) @ in[2m] + in[2m+1]
  for (int l = 0; l < 5; l++) {
    const f16* in = (l == 0) ? H + O_PC : H + O_F + (l - 1) * FLVL;
    long csin = (l == 0) ? CS_PC : CS_F;
    cudaStreamWaitEvent(s1, ev[3 + l], 0);
    mm(s1, dim3(16, l == 0 ? 2 : 1, 1), in, csin, 1024,
       H + O_P + (3 + l) * SZ, CS_P, 512,
       H + O_F + l * FLVL, CS_F, 512, nullptr, 0, 512,
       in + 512, csin, 1024);
  }
  cudaEventRecord(ev[15], s1);

  // ---- join + fused tail (folds 5..7 + finish) on s0 ----
  cudaStreamWaitEvent(s0, ev[15], 0);
  cudaStreamWaitEvent(s0, ev[14], 0);
  k_tail<<<128, 256, 0, s0>>>(Cm, yh, out);
}

// round 12
// speedup vs baseline: 1.0206x; 1.0206x over previous
#include <cuda_runtime.h>
#include <cuda_fp16.h>
#include <cstdint>

using f16 = __half;

// ---------------------------------------------------------------------------
// Scratch layout (fp16 hi/lo pairs: components at +0 and +cs)
// ---------------------------------------------------------------------------
constexpr long SZ    = 262144;                 // 512*512
constexpr long O_P   = 0;          constexpr long CS_P  = 11 * SZ;  // A^(2^j) j=0..10
constexpr long O_PT  = 22 * SZ;                                     // transposes
constexpr long O_W   = 44 * SZ;    constexpr long CS_W  = 4 * SZ;   // W 512x2048
constexpr long O_WT  = 52 * SZ;                                     // Wt 2048x512
constexpr long O_U   = 60 * SZ;    constexpr long CS_U  = 2 * SZ;   // U 256x2048
constexpr long O_PC  = 64 * SZ;    constexpr long CS_PC = SZ / 2;   // Pc 256x512
constexpr long O_F   = 65 * SZ;    constexpr long CS_F  = 2 * SZ;   // folds 8x128x512
constexpr long FLVL  = 65536;                  // 128 rows x 512 per fold level
constexpr long HTOT  = 69 * SZ;

constexpr int OF_PC  = 0;                      // chunk fp32 split-K accumulator
constexpr int OF_V   = 131072;                 // 306 x 256 weighted vectors
constexpr int OF_UAC = OF_V + 306 * 256;
constexpr int FTOT   = OF_UAC + 256;

__device__ __align__(16) f16   g_h[HTOT];
__device__ __align__(16) float g_f[FTOT];
__device__ unsigned g_bar2;

// ---------------------------------------------------------------------------
__device__ __forceinline__ void split2(float v, f16& h, f16& l) {
  h = __float2half_rn(v);
  l = __float2half_rn(v - __half2float(h));
}

// Merged head: cvtA | cvtB | cvtU | zero, branched on blockIdx.x
__global__ void k_init(const float* __restrict__ A, const float* __restrict__ B,
                       const float* __restrict__ uh)
{
  const int b = blockIdx.x, t = threadIdx.x;
  if (b < 1024) {                       // A -> P0 + PT0
    int i = b * 256 + t;
    f16 h, l; split2(A[i], h, l);
    int r = i >> 9, k = i & 511;
    g_h[O_P + i] = h; g_h[O_P + CS_P + i] = l;
    long tr = O_PT + (long)k * 512 + r;
    g_h[tr] = h; g_h[tr + CS_P] = l;
  } else if (b < 1536) {                // B -> W block7 + WT block7
    int i = (b - 1024) * 256 + t;
    f16 h, l; split2(B[i], h, l);
    int d = i >> 8, n = i & 255;
    long w = O_W + (long)d * 2048 + 1792 + n;
    g_h[w] = h; g_h[w + CS_W] = l;
    long tr = O_WT + (long)(1792 + n) * 512 + d;
    g_h[tr] = h; g_h[tr + CS_W] = l;
  } else if (b < 3584) {                // u_history -> U pair
    int i = (b - 1536) * 256 + t;
    f16 h, l; split2(uh[i], h, l);
    g_h[O_U + i] = h; g_h[O_U + CS_U + i] = l;
  } else {                              // zero fp32 scratch + fold region
    if (b == 3584 && t == 0) g_bar2 = 0;
    long i = (long)(b - 3584) * 256 + t;
    if (i < FTOT / 4) ((float4*)g_f)[i] = make_float4(0.f, 0.f, 0.f, 0.f);
    long j = i - FTOT / 4;
    if (j >= 0 && j < SZ / 2)
      ((uint4*)(g_h + O_F))[j] = make_uint4(0u, 0u, 0u, 0u);
  }
}

__global__ void k_cvtP() {
  int i = blockIdx.x * 256 + threadIdx.x;              // 131072
  f16 h, l; split2(g_f[OF_PC + i], h, l);
  g_h[O_PC + i] = h; g_h[O_PC + CS_PC + i] = l;
}

// ---------------------------------------------------------------------------
// Tensor-core GEMM (NT): C[m][n] = sum_k A[m][k]*Bt[n][k]  (+addsrc pair)
// fp16 2-way split, 3 products (hh, hl, lh), fp32 accumulate.
// CTA tile 64x32, full K=512 smem-resident. Loads issued as 8 commit groups
// (one per 64-wide K chunk) up front; compute interleaves wait_group(7-c)
// so only chunk-0 latency is exposed. 256 threads: kg2 x wm2 x wn2.
// ---------------------------------------------------------------------------
__device__ __forceinline__ void mma16816(float* c, const uint32_t* a, const uint32_t* b) {
  asm volatile(
    "mma.sync.aligned.m16n8k16.row.col.f32.f16.f16.f32 "
    "{%0,%1,%2,%3},{%4,%5,%6,%7},{%8,%9},{%0,%1,%2,%3};\n"
    : "+f"(c[0]), "+f"(c[1]), "+f"(c[2]), "+f"(c[3])
    : "r"(a[0]), "r"(a[1]), "r"(a[2]), "r"(a[3]), "r"(b[0]), "r"(b[1]));
}

__device__ __forceinline__ void ldsm4(uint32_t& r0, uint32_t& r1, uint32_t& r2,
                                      uint32_t& r3, uint32_t addr) {
  asm volatile("ldmatrix.sync.aligned.m8n8.x4.shared.b16 {%0,%1,%2,%3}, [%4];"
               : "=r"(r0), "=r"(r1), "=r"(r2), "=r"(r3) : "r"(addr));
}

__device__ __forceinline__ uint32_t s2u(const void* p) {
  uint32_t a;
  asm("{ .reg .u64 t; cvta.to.shared.u64 t, %1; cvt.u32.u64 %0, t; }"
      : "=r"(a) : "l"(p));
  return a;
}

__device__ __forceinline__ void cpa16(uint32_t d, const void* s) {
  asm volatile("cp.async.cg.shared.global [%0], [%1], 16;" :: "r"(d), "l"(s));
}

constexpr int LSK    = 520;            // full-K padded stride (halves)
constexpr int A_HLV  = 64 * LSK;       // per-component A region (halves)
constexpr int B_HLV  = 32 * LSK;
constexpr int B_OFF  = 2 * A_HLV;      // halves offset of B region
constexpr int DSM    = (2 * A_HLV + 2 * B_HLV) * 2;   // 199680 bytes

__global__ void __launch_bounds__(256) k_mma(
    const f16* __restrict__ A, long csA, int lda,
    const f16* __restrict__ B, long csB, int ldb,
    f16* C, long csC, int ldc, f16* Ct, int ldct, int ksl,
    const f16* __restrict__ ad, long csAd, int ldad, float* Cf)
{
  extern __shared__ __align__(16) char smem[];
  const int tid = threadIdx.x, lane = tid & 31, warp = tid >> 5;
  const int kg = warp >> 2, w4 = warp & 3;
  const int wm = w4 & 1, wn = w4 >> 1;       // warp tile m32 x n16
  const int bm = blockIdx.y * 64, bn = blockIdx.x * 32;
  const long k0 = (long)blockIdx.z * ksl;    // ksl == 512 always
  const int G = lane >> 2, T = lane & 3;
  const uint32_t sb = s2u(smem);
  float acc[2][2][4] = {};                   // [mt][nt][4]

  // ldmatrix per-thread byte offsets (within a component plane)
  const int aRowL = ((lane >> 3) & 1) * 8 + (lane & 7);
  const int aColL = ((lane >> 4) & 1) * 8;
  uint32_t aOff[2];
  aOff[0] = (uint32_t)((wm * 32 + aRowL) * LSK + aColL) * 2;
  aOff[1] = (uint32_t)((wm * 32 + 16 + aRowL) * LSK + aColL) * 2;
  const int bRowL = ((lane >> 4) & 1) * 8 + (lane & 7);
  const int bColL = ((lane >> 3) & 1) * 8;
  const uint32_t bOff = (uint32_t)((wn * 16 + bRowL) * LSK + bColL) * 2;

  // ---- issue ALL loads up front, ONE commit group per 64-wide K chunk ----
  {
    const int row0 = tid >> 3, colb = (tid & 7) * 8;
#pragma unroll
    for (int kq = 0; kq < 8; kq++) {
      const long kb = k0 + kq * 64 + colb;
      const uint32_t so = (uint32_t)(kq * 64 + colb);
#pragma unroll
      for (int c = 0; c < 2; c++) {
#pragma unroll
        for (int rg = 0; rg < 2; rg++) {
          const int row = row0 + rg * 32;
          cpa16(sb + (uint32_t)(c * A_HLV + row * LSK) * 2 + so * 2,
                A + c * csA + (long)(bm + row) * lda + kb);
        }
        cpa16(sb + (uint32_t)(B_OFF + c * B_HLV + row0 * LSK) * 2 + so * 2,
              B + c * csB + (long)(bn + row0) * ldb + kb);
      }
      asm volatile("cp.async.commit_group;");
    }
  }

  // ---- pipelined compute: wait chunk c, then its MMAs ----
  auto do_chunk = [&](int c0) {
#pragma unroll
    for (int q = 0; q < 2; q++) {
      const int it = c0 * 2 + q;
      const int kk = it * 32 + kg * 16;
      uint32_t aF[2][2][4], bF[2][2][2];
#pragma unroll
      for (int c = 0; c < 2; c++) {
#pragma unroll
        for (int mt = 0; mt < 2; mt++)
          ldsm4(aF[c][mt][0], aF[c][mt][1], aF[c][mt][2], aF[c][mt][3],
                sb + (uint32_t)(c * A_HLV + kk) * 2 + aOff[mt]);
        ldsm4(bF[c][0][0], bF[c][0][1], bF[c][1][0], bF[c][1][1],
              sb + (uint32_t)(B_OFF + c * B_HLV + kk) * 2 + bOff);
      }
#pragma unroll
      for (int mt = 0; mt < 2; mt++)
#pragma unroll
        for (int nt = 0; nt < 2; nt++) {
          mma16816(acc[mt][nt], aF[0][mt], bF[0][nt]);   // hh
          mma16816(acc[mt][nt], aF[0][mt], bF[1][nt]);   // hl
          mma16816(acc[mt][nt], aF[1][mt], bF[0][nt]);   // lh
        }
    }
  };

#define STEP(c, n) \
  do { asm volatile("cp.async.wait_group %0;" :: "n"(n) : "memory"); \
       __syncthreads(); do_chunk(c); } while (0)
  STEP(0, 7); STEP(1, 6); STEP(2, 5); STEP(3, 4);
  STEP(4, 3); STEP(5, 2); STEP(6, 1); STEP(7, 0);
#undef STEP
  __syncthreads();                      // before smem reuse for reduction

  // ---- kg split-K reduction through smem (64x33 fp32) ----
  float* red = (float*)smem;
  if (kg) {
#pragma unroll
    for (int mt = 0; mt < 2; mt++)
#pragma unroll
      for (int nt = 0; nt < 2; nt++)
#pragma unroll
        for (int h2 = 0; h2 < 2; h2++) {
          const int rl = wm * 32 + mt * 16 + G + h2 * 8;
          const int cl = wn * 16 + nt * 8 + T * 2;
          red[rl * 33 + cl]     = acc[mt][nt][h2 * 2];
          red[rl * 33 + cl + 1] = acc[mt][nt][h2 * 2 + 1];
        }
  }
  __syncthreads();
  if (!kg) {
#pragma unroll
    for (int mt = 0; mt < 2; mt++)
#pragma unroll
      for (int nt = 0; nt < 2; nt++)
#pragma unroll
        for (int h2 = 0; h2 < 2; h2++) {
          const int rl = wm * 32 + mt * 16 + G + h2 * 8;
          const int cl = wn * 16 + nt * 8 + T * 2;
          acc[mt][nt][h2 * 2]     += red[rl * 33 + cl];
          acc[mt][nt][h2 * 2 + 1] += red[rl * 33 + cl + 1];
        }
  }

  if (Cf) {
    if (!kg) {
#pragma unroll
      for (int mt = 0; mt < 2; mt++)
#pragma unroll
        for (int nt = 0; nt < 2; nt++)
#pragma unroll
          for (int h2 = 0; h2 < 2; h2++) {
            const int r = bm + wm * 32 + mt * 16 + G + h2 * 8;
            const int c0 = bn + wn * 16 + nt * 8 + T * 2;
            atomicAdd(&Cf[(long)r * ldc + c0],     acc[mt][nt][h2 * 2]);
            atomicAdd(&Cf[(long)r * ldc + c0 + 1], acc[mt][nt][h2 * 2 + 1]);
          }
    }
    return;
  }

  if (!kg) {
#pragma unroll
    for (int mt = 0; mt < 2; mt++)
#pragma unroll
      for (int nt = 0; nt < 2; nt++)
#pragma unroll
        for (int h2 = 0; h2 < 2; h2++) {
          const int rl = wm * 32 + mt * 16 + G + h2 * 8;
          const int cl = wn * 16 + nt * 8 + T * 2;
          const int r = bm + rl, c0 = bn + cl;
          float v0 = acc[mt][nt][h2 * 2], v1 = acc[mt][nt][h2 * 2 + 1];
          if (ad) {
            const long o0 = (long)r * ldad + c0;
            v0 += __half2float(ad[o0])     + __half2float(ad[csAd + o0]);
            v1 += __half2float(ad[o0 + 1]) + __half2float(ad[csAd + o0 + 1]);
          }
          f16 h0, l0, h1, l1;
          split2(v0, h0, l0); split2(v1, h1, l1);
          __half2 t;
          t.x = h0; t.y = h1; *(__half2*)&C[(long)r * ldc + c0] = t;
          t.x = l0; t.y = l1; *(__half2*)&C[csC + (long)r * ldc + c0] = t;
          if (Ct) { red[rl * 33 + cl] = v0; red[rl * 33 + cl + 1] = v1; }
        }
  }

  if (Ct) {
    __syncthreads();
    const int cl = tid >> 3, rb = (tid & 7) * 8;   // col 0..31, row block
    const long cb = (long)(bn + cl) * ldct + bm + rb;
#pragma unroll
    for (int j = 0; j < 8; j += 2) {
      float a0 = red[(rb + j) * 33 + cl];
      float a1 = red[(rb + j + 1) * 33 + cl];
      f16 h0, l0, h1, l1;
      split2(a0, h0, l0); split2(a1, h1, l1);
      __half2 t;
      t.x = h0; t.y = h1; *(__half2*)&Ct[cb + j] = t;
      t.x = l0; t.y = l1; *(__half2*)&Ct[csC + cb + j] = t;
    }
  }
}

// ---------------------------------------------------------------------------
// Fused tail: folds 5..7 (fp32 SIMT matvecs, grid-synced) + finish.
// ---------------------------------------------------------------------------
__global__ void __launch_bounds__(256) k_tail(
    const float* __restrict__ Cm, const float* __restrict__ yh, float* __restrict__ out)
{
  const int lane = threadIdx.x & 31;
  const int w = blockIdx.x * 8 + (threadIdx.x >> 5);
  const int NW = gridDim.x * 8;

  for (int l = 5; l <= 7; l++) {
    const int nv = 256 >> (l + 1);             // 4, 2, 1 output vectors
    const long pb = O_P + (long)(3 + l) * SZ;  // A^(8*2^l)
    const long inb = O_F + (long)(l - 1) * FLVL;
    for (int d = w; d < nv * 512; d += NW) {
      const int o = d >> 9, m = d & 511;
      float acc = 0.f;
#pragma unroll
      for (int j = 0; j < 16; j++) {
        const int k = lane + 32 * j;
        float pv = __half2float(g_h[pb + (long)m * 512 + k]) +
                   __half2float(g_h[pb + CS_P + (long)m * 512 + k]);
        float iv = __half2float(g_h[inb + (long)(2 * o) * 512 + k]) +
                   __half2float(g_h[inb + CS_F + (long)(2 * o) * 512 + k]);
        acc += pv * iv;
      }
#pragma unroll
      for (int off = 16; off; off >>= 1) acc += __shfl_xor_sync(~0u, acc, off);
      if (lane == 0) {
        float i1 = __half2float(g_h[inb + (long)(2 * o + 1) * 512 + m]) +
                   __half2float(g_h[inb + CS_F + (long)(2 * o + 1) * 512 + m]);
        float v = acc + i1;
        f16 h, lo; split2(v, h, lo);
        g_h[O_F + (long)l * FLVL + (long)o * 512 + m] = h;
        g_h[O_F + CS_F + (long)l * FLVL + (long)o * 512 + m] = lo;
      }
    }
    // software grid barrier
    __syncthreads();
    if (threadIdx.x == 0) {
      __threadfence();
      atomicAdd(&g_bar2, 1u);
      const unsigned tgt = gridDim.x * (unsigned)(l - 4);
      while (*((volatile unsigned*)&g_bar2) < tgt) {}
    }
    __syncthreads();
  }

  // finish: y_nat = yh[2047] - C s ; pred = y_nat + C v ; u_t copy
  if (w < 256) {
    const int r = w;
    const float* crow = Cm + r * 512;
    const long so = O_F + 7L * FLVL;
    const long vo = O_F + 127L * 512;
    float ds = 0.f, dv = 0.f;
#pragma unroll
    for (int j = 0; j < 16; j++) {
      const int k = lane + 32 * j; const float c = crow[k];
      ds += c * (__half2float(g_h[so + k]) + __half2float(g_h[so + CS_F + k]));
      dv += c * (__half2float(g_h[vo + k]) + __half2float(g_h[vo + CS_F + k]));
    }
#pragma unroll
    for (int off = 16; off; off >>= 1) {
      ds += __shfl_xor_sync(~0u, ds, off);
      dv += __shfl_xor_sync(~0u, dv, off);
    }
    if (lane == 0) {
      float yn = yh[2047 * 256 + r] - ds;
      out[r] = yn; out[256 + r] = yn + dv; out[512 + r] = g_f[OF_UAC + r];
    }
  }
}

// ---------------------------------------------------------------------------
// u_t phase (fp32, unchanged)
// ---------------------------------------------------------------------------
__global__ void k_prep(const float* __restrict__ ynh, const float* __restrict__ phi,
                       const float* __restrict__ pht, const float* __restrict__ sigma,
                       const float* __restrict__ lam)
{
  const int x = blockIdx.x, p = threadIdx.x;
  float* V = g_f + OF_V;
#define YREV(j) ynh[(2047 - (j)) * 256 + p]
  if (x == 0) {
    V[p] = YREV(0);
  } else if (x < 17) {
    int i = x - 1; float acc = 0.f;
    for (int j = 0; j < 24; j++) acc += pht[j * 16 + i] * YREV(1 + j);
    V[x * 256 + p] = sqrtf(sqrtf(lam[i])) * acc;
  } else if (x < 34) {
    int l = x - 17; float acc = 0.f;
    for (int k = 0; k < 25; k++) acc += phi[k * 17 + l] * YREV(k);
    V[x * 256 + p] = sqrtf(sqrtf(sigma[l])) * acc;
  } else {
    int idx = x - 34, i = idx / 17, l = idx % 17;
    __shared__ float cm[48];
    if (p < 48) {
      int jlo = p > 24 ? p - 24 : 0, jhi = p < 23 ? p : 23;
      float s = 0.f;
      for (int j = jlo; j <= jhi; j++) s += pht[j * 16 + i] * phi[(p - j) * 17 + l];
      cm[p] = s;
    }
    __syncthreads();
    float acc = 0.f;
    for (int m = 0; m < 48; m++) acc += cm[m] * YREV(2 + m);
    V[x * 256 + p] = sqrtf(sqrtf(lam[i])) * sqrtf(sqrtf(sigma[l])) * acc;
  }
#undef YREV
}

__global__ void __launch_bounds__(256) k_matvec(
    const float* __restrict__ M, const float* __restrict__ Mbar)
{
  const int task = (blockIdx.x * 256 + threadIdx.x) >> 5;
  const int lane = threadIdx.x & 31;
  const int x = task >> 8, n = task & 255;
  const float* row = (x < 17 ? Mbar + x * 65536 : M + (x - 17) * 65536) + n * 256;
  const float* v = g_f + OF_V + x * 256;
  float acc = 0.f;
#pragma unroll
  for (int j = 0; j < 2; j++) {
    float4 a = ((const float4*)row)[lane + 32 * j];
    float4 b = ((const float4*)v)[lane + 32 * j];
    acc += a.x * b.x + a.y * b.y + a.z * b.z + a.w * b.w;
  }
#pragma unroll
  for (int off = 16; off; off >>= 1) acc += __shfl_xor_sync(~0u, acc, off);
  if (lane == 0) atomicAdd(&g_f[OF_UAC + n], acc);
}

// ---------------------------------------------------------------------------
static inline void mm(cudaStream_t st, dim3 g, const f16* A, long csA, int lda,
                      const f16* B, long csB, int ldb,
                      f16* C, long csC, int ldc, f16* Ct, int ldct, int ksl,
                      const f16* ad = nullptr, long csAd = 0, int ldad = 0,
                      float* Cf = nullptr)
{
  k_mma<<<g, 256, DSM, st>>>(A, csA, lda, B, csB, ldb, C, csC, ldc, Ct, ldct, ksl,
                             ad, csAd, ldad, Cf);
}

extern "C" void kernel_launch(void* const* d_in, const int* in_sizes, int n_in,
                              void* d_out, int out_size)
{
  const float* A   = (const float*)d_in[0];
  const float* Bm  = (const float*)d_in[1];
  const float* Cm  = (const float*)d_in[2];
  const float* Mi  = (const float*)d_in[3];
  const float* Mb  = (const float*)d_in[4];
  const float* sig = (const float*)d_in[5];
  const float* phi = (const float*)d_in[6];
  const float* lam = (const float*)d_in[7];
  const float* pht = (const float*)d_in[8];
  const float* yh  = (const float*)d_in[9];
  const float* uh  = (const float*)d_in[10];
  const float* ynh = (const float*)d_in[11];
  float* out = (float*)d_out;

  // One-time infra (created on the uncaptured correctness call; no device mem)
  static bool inited = false;
  static cudaStream_t s1, s2;
  static cudaEvent_t ev[16];
  if (!inited) {
    cudaStreamCreateWithFlags(&s1, cudaStreamNonBlocking);
    cudaStreamCreateWithFlags(&s2, cudaStreamNonBlocking);
    for (int i = 0; i < 16; i++)
      cudaEventCreateWithFlags(&ev[i], cudaEventDisableTiming);
    cudaFuncSetAttribute(k_mma, cudaFuncAttributeMaxDynamicSharedMemorySize, DSM);
    inited = true;
  }
  cudaStream_t s0 = 0;

  void* p;
  cudaGetSymbolAddress(&p, g_h); f16* H = (f16*)p;
  cudaGetSymbolAddress(&p, g_f); float* F = (float*)p;

  // ---- head (s0) ----
  k_init<<<4304, 256, 0, s0>>>(A, Bm, uh);
  cudaEventRecord(ev[0], s0);

  // ---- s0: squaring chain A^2 .. A^1024, event after each ----
  for (int j = 1; j <= 10; j++) {
    mm(s0, dim3(16, 8, 1), H + O_P + (j - 1) * SZ, CS_P, 512,
       H + O_PT + (j - 1) * SZ, CS_P, 512,
       H + O_P + j * SZ, CS_P, 512, H + O_PT + j * SZ, 512, 512);
    cudaEventRecord(ev[j], s0);
  }

  // ---- s2: u_t phase, fully parallel ----
  cudaStreamWaitEvent(s2, ev[0], 0);
  k_prep<<<306, 256, 0, s2>>>(ynh, phi, pht, sig, lam);
  k_matvec<<<306 * 32, 256, 0, s2>>>(Mi, Mb);
  cudaEventRecord(ev[14], s2);

  // ---- s1: W build -> chunk -> folds 0..4 ----
  cudaStreamWaitEvent(s1, ev[0], 0);
  // W block6 = A @ B (B operand = WT block7), dual-write WT block6
  mm(s1, dim3(8, 8, 1), H + O_P, CS_P, 512, H + O_WT + 1792L * 512, CS_W, 512,
     H + O_W + 1536, CS_W, 2048, H + O_WT + 1536L * 512, 512, 512);
  // W blocks 4,5 = A^2 @ blocks 6,7
  cudaStreamWaitEvent(s1, ev[1], 0);
  mm(s1, dim3(16, 8, 1), H + O_P + SZ, CS_P, 512, H + O_WT + 1536L * 512, CS_W, 512,
     H + O_W + 1024, CS_W, 2048, H + O_WT + 1024L * 512, 512, 512);
  // W blocks 0..3 = A^4 @ blocks 4..7
  cudaStreamWaitEvent(s1, ev[2], 0);
  mm(s1, dim3(32, 8, 1), H + O_P + 2 * SZ, CS_P, 512, H + O_WT + 1024L * 512, CS_W, 512,
     H + O_W, CS_W, 2048, H + O_WT, 512, 512);
  // chunk partials: Pc = U @ W^T, split-K=4, fp32 atomics
  mm(s1, dim3(16, 4, 4), H + O_U, CS_U, 2048, H + O_W, CS_W, 2048,
     nullptr, 0, 512, nullptr, 0, 512, nullptr, 0, 0, F + OF_PC);
  k_cvtP<<<512, 256, 0, s1>>>();
  // fold levels 0..4: out[m] = A^(8*2^l) @ in[2m] + in[2m+1]
  for (int l = 0; l < 5; l++) {
    const f16* in = (l == 0) ? H + O_PC : H + O_F + (l - 1) * FLVL;
    long csin = (l == 0) ? CS_PC : CS_F;
    cudaStreamWaitEvent(s1, ev[3 + l], 0);
    mm(s1, dim3(16, l == 0 ? 2 : 1, 1), in, csin, 1024,
       H + O_P + (3 + l) * SZ, CS_P, 512,
       H + O_F + l * FLVL, CS_F, 512, nullptr, 0, 512,
       in + 512, csin, 1024);
  }
  cudaEventRecord(ev[15], s1);

  // ---- join + fused tail (folds 5..7 + finish) on s0 ----
  cudaStreamWaitEvent(s0, ev[15], 0);
  cudaStreamWaitEvent(s0, ev[14], 0);
  k_tail<<<128, 256, 0, s0>>>(Cm, yh, out);
}